// round 6
// baseline (speedup 1.0000x reference)
#include <cuda_runtime.h>

// FIRApply: y[t] = sum_{k=0}^{15} b[k] * x[t-k], zero initial state.
// x: [64, 480000] f32, b: [16] f32, y: [64, 480000] f32.
//
// Layout: thread lane i owns 4 consecutive outputs at t0 = tile + 4*i.
// Its 16-float history is exactly the float4 loads of lanes i-1..i-4,
// obtained via shfl_up (no extra L1 wavefronts). All gmem accesses are
// fully coalesced LDG.128/STG.128 (4 wavefronts per warp-instruction).

#define BATCH  64
#define T_LEN  480000
#define NTAPS  16
#define OPT    4
#define TPB    256
#define OPB    (OPT*TPB)   // 1024 outputs per block

__constant__ float c_b[NTAPS];

__device__ __forceinline__ float4 shfl_up_f4(float4 v, int d) {
    float4 r;
    r.x = __shfl_up_sync(0xffffffffu, v.x, d);
    r.y = __shfl_up_sync(0xffffffffu, v.y, d);
    r.z = __shfl_up_sync(0xffffffffu, v.z, d);
    r.w = __shfl_up_sync(0xffffffffu, v.w, d);
    return r;
}

__global__ __launch_bounds__(TPB)
void fir_kernel(const float* __restrict__ x,
                float* __restrict__ y)
{
    const int row  = blockIdx.y;
    const int t0   = blockIdx.x * OPB + threadIdx.x * OPT;
    const int lane = threadIdx.x & 31;
    const bool act = (t0 < T_LEN);            // ragged last tile

    const float* __restrict__ xr = x + (long long)row * T_LEN;
    float*       __restrict__ yr = y + (long long)row * T_LEN;

    // Own float4 (dense, fully coalesced). Inactive lanes (highest in warp)
    // load zero; their value is never consumed by shfl_up of active lanes.
    float4 A = make_float4(0.f, 0.f, 0.f, 0.f);
    if (act) A = __ldg(reinterpret_cast<const float4*>(xr + t0));

    // History from neighbors: B_d = A of lane (i-d) = x[t0-4d .. t0-4d+3]
    float4 B1 = shfl_up_f4(A, 1);
    float4 B2 = shfl_up_f4(A, 2);
    float4 B3 = shfl_up_f4(A, 3);
    float4 B4 = shfl_up_f4(A, 4);

    // Warp-edge lanes: fetch out-of-warp history from gmem (zero before t=0).
    // g = t0-4d is a multiple of 4, so each float4 is entirely in/out of range.
    if (act) {
        if (lane < 1) { int g = t0 - 4;
            B1 = (g >= 0) ? __ldg(reinterpret_cast<const float4*>(xr + g))
                          : make_float4(0.f, 0.f, 0.f, 0.f); }
        if (lane < 2) { int g = t0 - 8;
            B2 = (g >= 0) ? __ldg(reinterpret_cast<const float4*>(xr + g))
                          : make_float4(0.f, 0.f, 0.f, 0.f); }
        if (lane < 3) { int g = t0 - 12;
            B3 = (g >= 0) ? __ldg(reinterpret_cast<const float4*>(xr + g))
                          : make_float4(0.f, 0.f, 0.f, 0.f); }
        if (lane < 4) { int g = t0 - 16;
            B4 = (g >= 0) ? __ldg(reinterpret_cast<const float4*>(xr + g))
                          : make_float4(0.f, 0.f, 0.f, 0.f); }
    }

    // Window w[q] = x[t0 - 16 + q], q = 0..19
    float w[20];
    w[ 0] = B4.x; w[ 1] = B4.y; w[ 2] = B4.z; w[ 3] = B4.w;
    w[ 4] = B3.x; w[ 5] = B3.y; w[ 6] = B3.z; w[ 7] = B3.w;
    w[ 8] = B2.x; w[ 9] = B2.y; w[10] = B2.z; w[11] = B2.w;
    w[12] = B1.x; w[13] = B1.y; w[14] = B1.z; w[15] = B1.w;
    w[16] = A.x;  w[17] = A.y;  w[18] = A.z;  w[19] = A.w;

    // y[t0+o] = sum_k c_b[k] * w[o + 16 - k]
    float acc[OPT];
#pragma unroll
    for (int o = 0; o < OPT; o++) {
        float s = 0.0f;
#pragma unroll
        for (int k = 0; k < NTAPS; k++)
            s = fmaf(c_b[k], w[o + 16 - k], s);
        acc[o] = s;
    }

    if (act)
        *reinterpret_cast<float4*>(yr + t0) =
            make_float4(acc[0], acc[1], acc[2], acc[3]);
}

extern "C" void kernel_launch(void* const* d_in, const int* in_sizes, int n_in,
                              void* d_out, int out_size)
{
    const float* x = (const float*)d_in[0];
    const float* b = (const float*)d_in[1];
    float* y = (float*)d_out;

    cudaMemcpyToSymbolAsync(c_b, b, NTAPS * sizeof(float), 0,
                            cudaMemcpyDeviceToDevice);

    dim3 grid((T_LEN + OPB - 1) / OPB, BATCH);  // (469, 64)
    fir_kernel<<<grid, TPB>>>(x, y);
}

// round 7
// speedup vs baseline: 1.3740x; 1.3740x over previous
#include <cuda_runtime.h>

// FIRApply: y[t] = sum_{k=0}^{15} b[k] * x[t-k], zero initial state.
// x: [64, 480000] f32, b: [16] f32, y: [64, 480000] f32.
//
// Dense mapping: lane i owns 4 consecutive outputs at t0 = tile + 4*i.
// The 20-float window x[t0-16 .. t0+3] is fetched as 5 LDG.128 at offsets
// t0-16, -12, -8, -4, 0. Every one of these is dense across the warp
// (16B thread stride) -> exactly 4 L1 wavefronts per warp-instruction,
// the coalesced minimum. The 5x read overlap hits L1 (wavefront cost is
// per-line-touched, not per-byte); DRAM traffic is unchanged. No shuffles,
// no shared memory, no extra ALU work.

#define BATCH  64
#define T_LEN  480000
#define NTAPS  16
#define OPT    4
#define TPB    256
#define OPB    (OPT*TPB)   // 1024 outputs per block

__constant__ float c_b[NTAPS];

__global__ __launch_bounds__(TPB)
void fir_kernel(const float* __restrict__ x,
                float* __restrict__ y)
{
    const int row = blockIdx.y;
    const int t0  = blockIdx.x * OPB + threadIdx.x * OPT;
    if (t0 >= T_LEN) return;                 // ragged last tile only

    const float* __restrict__ xr = x + (long long)row * T_LEN;
    float*       __restrict__ yr = y + (long long)row * T_LEN;

    // Window w[q] = x[t0 - 16 + q], q = 0..19, via 5 coalesced float4 loads.
    // g = t0 - 16 + 4c is a multiple of 4, so each float4 is entirely
    // in-range or entirely before t=0 (zero history). t0+3 < T_LEN always
    // (T_LEN % 4 == 0).
    float w[20];
#pragma unroll
    for (int c = 0; c < 5; c++) {
        const int g = t0 - 16 + 4 * c;
        float4 v = (g >= 0)
            ? __ldg(reinterpret_cast<const float4*>(xr + g))
            : make_float4(0.f, 0.f, 0.f, 0.f);
        w[4*c+0] = v.x; w[4*c+1] = v.y; w[4*c+2] = v.z; w[4*c+3] = v.w;
    }

    // y[t0+o] = sum_k c_b[k] * w[o + 16 - k]
    float acc[OPT];
#pragma unroll
    for (int o = 0; o < OPT; o++) {
        float s = 0.0f;
#pragma unroll
        for (int k = 0; k < NTAPS; k++)
            s = fmaf(c_b[k], w[o + 16 - k], s);
        acc[o] = s;
    }

    *reinterpret_cast<float4*>(yr + t0) =
        make_float4(acc[0], acc[1], acc[2], acc[3]);
}

extern "C" void kernel_launch(void* const* d_in, const int* in_sizes, int n_in,
                              void* d_out, int out_size)
{
    const float* x = (const float*)d_in[0];
    const float* b = (const float*)d_in[1];
    float* y = (float*)d_out;

    cudaMemcpyToSymbolAsync(c_b, b, NTAPS * sizeof(float), 0,
                            cudaMemcpyDeviceToDevice);

    dim3 grid((T_LEN + OPB - 1) / OPB, BATCH);  // (469, 64)
    fir_kernel<<<grid, TPB>>>(x, y);
}